// round 6
// baseline (speedup 1.0000x reference)
#include <cuda_runtime.h>

// ---- packed f32x2 helpers (sm_103a) ----
#define FMA_F32X2(d, a, b, c) \
    asm("fma.rn.f32x2 %0, %1, %2, %3;" : "=l"(d) : "l"(a), "l"(b), "l"(c))
#define MUL_F32X2(d, a, b) \
    asm("mul.rn.f32x2 %0, %1, %2;" : "=l"(d) : "l"(a), "l"(b))
#define PACK_F32X2(d, lo, hi) \
    asm("mov.b64 %0, {%1, %2};" : "=l"(d) : "f"(lo), "f"(hi))
#define UNPACK_F32X2(lo, hi, s) \
    asm("mov.b64 {%0, %1}, %2;" : "=f"(lo), "=f"(hi) : "l"(s))

// Scratch (no device allocation allowed).
// Transposed layout: g_part[entry][block]; blocks 8b..8b+7 belong to batch b,
// so each batch's 8 partials of one entry are two aligned float4s.
__device__ __align__(16) float g_part[36][32];
__device__ unsigned int g_count = 0;

// Weight of packed upper-triangular entry e=(i,j), i<=j, of the 8x8 moment
// matrix M in loss_b = sum_e w_e * M_b[e]^2.
__constant__ float c_w[36] = {
    1.f, 2.f, 2.f, 2.f, -2.f, -2.f, -2.f, -2.f,   // i=0
    1.f, 2.f, 2.f, -2.f, -2.f, -2.f, -2.f,        // i=1
    1.f, 2.f, -2.f, -2.f, -2.f, -2.f,             // i=2
    1.f, -2.f, -2.f, -2.f, -2.f,                  // i=3
    1.f, 2.f, 2.f, 2.f,                           // i=4
    1.f, 2.f, 2.f,                                // i=5
    1.f, 2.f,                                     // i=6
    1.f                                           // i=7
};

// grid = 32 blocks (8 slices per batch), 128 threads (1 warp per SMSP).
// Each thread owns one float4 group (4 spatial positions), processed as two
// f32x2-packed position pairs. v_n = [p_n/||p_n||, s_n/||s_n||] in R^8;
// block accumulates 36 unique entries of sum_n v_n v_n^T. Last arriving
// block's warp 0 reduces per-BATCH and evaluates
//   loss = sum_b (||PP^T||^2 - 2||PS^T||^2 + ||SS^T||^2) / (B*N*N).
__global__ void __launch_bounds__(128, 1)
cosine_ssm_fused_kernel(const float* __restrict__ xp,
                        const float* __restrict__ xs,
                        float* __restrict__ out)
{
    constexpr int N = 4096;
    const int blk   = blockIdx.x;
    const int b     = blk >> 3;       // batch (8 blocks per batch)
    const int slice = blk & 7;
    const int t     = threadIdx.x;
    const int warp  = t >> 5;
    const int lane  = t & 31;

    const float* pb = xp + b * 4 * N;
    const float* sb = xs + b * 4 * N;
    const int g = (slice * 512) + t * 4;   // starting spatial index

    // Load each channel's float4 as two packed f32x2 (free pairing from LDG.128).
    unsigned long long pvv[4][2], svv[4][2];
#pragma unroll
    for (int c = 0; c < 4; ++c) {
        ulonglong2 a = *reinterpret_cast<const ulonglong2*>(pb + c * N + g);
        pvv[c][0] = a.x; pvv[c][1] = a.y;
        ulonglong2 q = *reinterpret_cast<const ulonglong2*>(sb + c * N + g);
        svv[c][0] = q.x; svv[c][1] = q.y;
    }

    unsigned long long acc2[36];
#pragma unroll
    for (int i = 0; i < 36; ++i) acc2[i] = 0ull;   // {0.f, 0.f}

#pragma unroll
    for (int pr = 0; pr < 2; ++pr) {               // position pair
        // packed sum of squares over channels
        unsigned long long sp2, ss2;
        MUL_F32X2(sp2, pvv[0][pr], pvv[0][pr]);
        MUL_F32X2(ss2, svv[0][pr], svv[0][pr]);
#pragma unroll
        for (int c = 1; c < 4; ++c) {
            FMA_F32X2(sp2, pvv[c][pr], pvv[c][pr], sp2);
            FMA_F32X2(ss2, svv[c][pr], svv[c][pr], ss2);
        }
        float spA, spB, ssA, ssB;
        UNPACK_F32X2(spA, spB, sp2);
        UNPACK_F32X2(ssA, ssB, ss2);
        // x / max(||x||, 1e-12) == x * rsqrt(max(||x||^2, 1e-24))
        float ipA = rsqrtf(fmaxf(spA, 1e-24f));
        float ipB = rsqrtf(fmaxf(spB, 1e-24f));
        float isA = rsqrtf(fmaxf(ssA, 1e-24f));
        float isB = rsqrtf(fmaxf(ssB, 1e-24f));
        unsigned long long ip2, is2;
        PACK_F32X2(ip2, ipA, ipB);
        PACK_F32X2(is2, isA, isB);

        unsigned long long vv[8];
#pragma unroll
        for (int c = 0; c < 4; ++c) {
            MUL_F32X2(vv[c],     pvv[c][pr], ip2);
            MUL_F32X2(vv[4 + c], svv[c][pr], is2);
        }
        int idx = 0;
#pragma unroll
        for (int i = 0; i < 8; ++i)
#pragma unroll
            for (int jj = i; jj < 8; ++jj) {
                FMA_F32X2(acc2[idx], vv[i], vv[jj], acc2[idx]);
                ++idx;
            }
    }

    // Fold packed halves, then 2 butterfly rounds: lanes 0..7 hold
    // sums over lanes {l, l+8, l+16, l+24}.
    float acc[36];
#pragma unroll
    for (int i = 0; i < 36; ++i) {
        float lo, hi;
        UNPACK_F32X2(lo, hi, acc2[i]);
        acc[i] = lo + hi;
    }
#pragma unroll
    for (int off = 16; off >= 8; off >>= 1)
#pragma unroll
        for (int i = 0; i < 36; ++i)
            acc[i] += __shfl_down_sync(0xffffffffu, acc[i], off);

    // Padded smem: stride 37 (== 5 mod 32) -> conflict-free column reads.
    __shared__ float red[32][37];
    if (lane < 8) {
        float* row = red[warp * 8 + lane];
#pragma unroll
        for (int i = 0; i < 36; ++i) row[i] = acc[i];
    }
    __syncthreads();

    // Warp 0 only: cross-row sum, publish, arrive, (maybe) finalize.
    if (warp != 0) return;

    {
        float s = 0.0f;
#pragma unroll
        for (int r = 0; r < 32; ++r) s += red[r][lane];
        g_part[lane][blk] = s;
        if (lane < 4) {
            float s2 = 0.0f;
#pragma unroll
            for (int r = 0; r < 32; ++r) s2 += red[r][32 + lane];
            g_part[32 + lane][blk] = s2;
        }
    }
    __syncwarp();

    unsigned int old = 0;
    if (lane == 0) {
        __threadfence();      // publish this block's g_part column
        old = atomicAdd(&g_count, 1u);
    }
    old = __shfl_sync(0xffffffffu, old, 0);
    if (old != 31u) return;

    // ---- last block, warp 0: per-BATCH reduce + weighted square ----
    __threadfence();          // acquire: make all blocks' g_part visible

    float val = 0.0f;
    {
        const float4* r = reinterpret_cast<const float4*>(g_part[lane]);
        float ssum = 0.0f;
#pragma unroll
        for (int bb = 0; bb < 4; ++bb) {
            float4 q0 = __ldcg(r + bb * 2);
            float4 q1 = __ldcg(r + bb * 2 + 1);
            float m = ((q0.x + q0.y) + (q0.z + q0.w))
                    + ((q1.x + q1.y) + (q1.z + q1.w));
            ssum += m * m;
        }
        val = c_w[lane] * ssum;
    }
    if (lane < 4) {
        const float4* r = reinterpret_cast<const float4*>(g_part[32 + lane]);
        float ssum = 0.0f;
#pragma unroll
        for (int bb = 0; bb < 4; ++bb) {
            float4 q0 = __ldcg(r + bb * 2);
            float4 q1 = __ldcg(r + bb * 2 + 1);
            float m = ((q0.x + q0.y) + (q0.z + q0.w))
                    + ((q1.x + q1.y) + (q1.z + q1.w));
            ssum += m * m;
        }
        val += c_w[32 + lane] * ssum;
    }

#pragma unroll
    for (int off = 16; off > 0; off >>= 1)
        val += __shfl_down_sync(0xffffffffu, val, off);

    if (lane == 0) {
        out[0] = val * (1.0f / (4.0f * 4096.0f * 4096.0f));
        g_count = 0;   // reset for the next graph replay
    }
}

extern "C" void kernel_launch(void* const* d_in, const int* in_sizes, int n_in,
                              void* d_out, int out_size)
{
    const float* xp = (const float*)d_in[0];  // x_pred [4,4,64,64] fp32
    const float* xs = (const float*)d_in[1];  // x_src  [4,4,64,64] fp32
    cosine_ssm_fused_kernel<<<32, 128>>>(xp, xs, (float*)d_out);
}